// round 1
// baseline (speedup 1.0000x reference)
#include <cuda_runtime.h>
#include <math.h>
#include <stdint.h>

#define B_SI 4.1491f
#define B_O  5.803f
#define TET_CUTOFF 3.9f
#define PI_F 3.14159265358979323846f

#define MAXS 8
#define MAXNR 256
#define MAXN 4096

// scratch (no allocations allowed)
__device__ float g_hist[MAXS * MAXNR];
__device__ float g_A[MAXS * MAXNR];
__device__ float g_inv[MAXS][9];
__device__ float g_V[MAXS];
__device__ float g_rho[MAXS];
__device__ float g_bn[MAXN];

// ---------------------------------------------------------------------------
// Setup: mean scattering length, normalized b, 3x3 cell inverses, det, zero hist
// ---------------------------------------------------------------------------
__global__ void k_setup(const float* __restrict__ cell,
                        const int* __restrict__ zn,
                        int S, int N, int NR)
{
    __shared__ float red[256];
    int t = threadIdx.x;

    float acc = 0.f;
    for (int i = t; i < N; i += 256) acc += (zn[i] == 14) ? B_SI : B_O;
    red[t] = acc;
    __syncthreads();
    for (int o = 128; o > 0; o >>= 1) {
        if (t < o) red[t] += red[t + o];
        __syncthreads();
    }
    float meanb = red[0] / (float)N;

    for (int i = t; i < N; i += 256)
        g_bn[i] = ((zn[i] == 14) ? B_SI : B_O) / meanb;

    for (int i = t; i < S * NR; i += 256) g_hist[i] = 0.f;

    if (t < S) {
        const float* a = cell + 9 * t;
        float det = a[0]*(a[4]*a[8]-a[5]*a[7])
                  - a[1]*(a[3]*a[8]-a[5]*a[6])
                  + a[2]*(a[3]*a[7]-a[4]*a[6]);
        float id = 1.f / det;
        float* inv = g_inv[t];
        inv[0] = (a[4]*a[8]-a[5]*a[7])*id;
        inv[1] = (a[2]*a[7]-a[1]*a[8])*id;
        inv[2] = (a[1]*a[5]-a[2]*a[4])*id;
        inv[3] = (a[5]*a[6]-a[3]*a[8])*id;
        inv[4] = (a[0]*a[8]-a[2]*a[6])*id;
        inv[5] = (a[2]*a[3]-a[0]*a[5])*id;
        inv[6] = (a[3]*a[7]-a[4]*a[6])*id;
        inv[7] = (a[1]*a[6]-a[0]*a[7])*id;
        inv[8] = (a[0]*a[4]-a[1]*a[3])*id;
        float V = fabsf(det);
        g_V[t]   = V;
        g_rho[t] = (float)N / V;
    }
}

// ---------------------------------------------------------------------------
// Pair histogram: grid = S * TI * TI blocks of 256 threads.
// Each block: one 256-wide i-tile vs one 256-wide j-tile.
// Gaussian support truncated at +-8*sigma = +-4*dr (error ~e^-32).
// Per-warp shared histograms, then block reduce -> global atomics.
// ---------------------------------------------------------------------------
__global__ void __launch_bounds__(256)
k_pairs(const float* __restrict__ pos,
        const float* __restrict__ cell,
        const float* __restrict__ rbins,
        int N, int NR, int TI)
{
    __shared__ float s_r[MAXNR];
    __shared__ float s_jx[256], s_jy[256], s_jz[256], s_jb[256];
    __shared__ float s_h[8][MAXNR];

    int bid = blockIdx.x;
    int jt = bid % TI;
    int it = (bid / TI) % TI;
    int s  = bid / (TI * TI);
    int t  = threadIdx.x;

    for (int k = t; k < NR; k += 256) s_r[k] = rbins[k];
    for (int k = t; k < 8 * MAXNR; k += 256) (&s_h[0][0])[k] = 0.f;

    // uniform per-block loads of cell and its inverse
    const float* cc = cell + 9 * s;
    float c0 = cc[0], c1 = cc[1], c2 = cc[2];
    float c3 = cc[3], c4 = cc[4], c5 = cc[5];
    float c6 = cc[6], c7 = cc[7], c8 = cc[8];
    const float* iv = g_inv[s];
    float i0 = iv[0], i1 = iv[1], i2 = iv[2];
    float i3 = iv[3], i4 = iv[4], i5 = iv[5];
    float i6 = iv[6], i7 = iv[7], i8 = iv[8];

    int jbase = jt * 256;
    int jn = N - jbase; if (jn > 256) jn = 256;
    if (t < jn) {
        const float* p = pos + ((size_t)s * N + jbase + t) * 3;
        s_jx[t] = p[0]; s_jy[t] = p[1]; s_jz[t] = p[2];
        s_jb[t] = g_bn[jbase + t];
    }
    __syncthreads();

    float dr = s_r[1] - s_r[0];
    float r0 = s_r[0];
    float inv_dr  = 1.f / dr;
    float inv_sig = 2.f / dr;           // 1/sigma, sigma = dr/2
    float Wd   = 4.f * dr;              // 8 sigma window
    float lim  = s_r[NR - 1] + Wd;
    float lim2 = lim * lim;

    float* wh = s_h[t >> 5];

    int i = it * 256 + t;
    if (i < N) {
        const float* p = pos + ((size_t)s * N + i) * 3;
        float xi = p[0], yi = p[1], zi = p[2];
        float bi = g_bn[i];

        for (int j = 0; j < jn; j++) {
            int jg = jbase + j;
            if (jg == i) continue;
            float dx = s_jx[j] - xi;
            float dy = s_jy[j] - yi;
            float dz = s_jz[j] - zi;
            // frac = disp @ inv_cell  (row-vector)
            float f0 = dx * i0 + dy * i3 + dz * i6;
            float f1 = dx * i1 + dy * i4 + dz * i7;
            float f2 = dx * i2 + dy * i5 + dz * i8;
            f0 -= rintf(f0); f1 -= rintf(f1); f2 -= rintf(f2);
            // disp = frac @ cell
            float gx = f0 * c0 + f1 * c3 + f2 * c6;
            float gy = f0 * c1 + f1 * c4 + f2 * c7;
            float gz = f0 * c2 + f1 * c5 + f2 * c8;
            float d2 = gx * gx + gy * gy + gz * gz;
            if (d2 > lim2) continue;
            float dist = sqrtf(d2 + 1e-12f);
            float w = bi * s_jb[j];
            int kLO = (int)ceilf((dist - Wd - r0) * inv_dr);
            int kHI = (int)floorf((dist + Wd - r0) * inv_dr);
            if (kLO < 0) kLO = 0;
            if (kHI > NR - 1) kHI = NR - 1;
            for (int k = kLO; k <= kHI; k++) {
                float tt = (dist - s_r[k]) * inv_sig;
                atomicAdd(&wh[k], w * __expf(-0.5f * tt * tt));
            }
        }
    }
    __syncthreads();

    for (int k = t; k < NR; k += 256) {
        float sum = s_h[0][k] + s_h[1][k] + s_h[2][k] + s_h[3][k]
                  + s_h[4][k] + s_h[5][k] + s_h[6][k] + s_h[7][k];
        atomicAdd(&g_hist[s * NR + k], sum);
    }
}

// ---------------------------------------------------------------------------
// Finalize G_r, T_r; stash (G-1)*r^2 for S_Q
// ---------------------------------------------------------------------------
__global__ void k_final(const float* __restrict__ rbins, int N, int NR,
                        float* __restrict__ outG, float* __restrict__ outT)
{
    int s = blockIdx.x;
    float dr = rbins[1] - rbins[0];
    float sigma = 0.5f * dr;
    float kern = dr / (sigma * sqrtf(2.f * PI_F));
    float V = g_V[s], rho = g_rho[s];
    float cG = V / ((float)N * (float)N * 4.f * PI_F * dr);
    for (int r = threadIdx.x; r < NR; r += blockDim.x) {
        float rv = rbins[r];
        float G = g_hist[s * NR + r] * kern * cG / (rv * rv);
        outG[s * NR + r] = G;
        outT[s * NR + r] = 4.f * PI_F * rho * rv * G;
        g_A[s * NR + r] = (G - 1.f) * rv * rv;
    }
}

// ---------------------------------------------------------------------------
// S_Q: per-system sinc-weighted sum over r
// ---------------------------------------------------------------------------
__global__ void k_sq(const float* __restrict__ rbins,
                     const float* __restrict__ qbins,
                     int NR, int NQ, float* __restrict__ outS)
{
    __shared__ float sA[MAXNR], sR[MAXNR];
    int s = blockIdx.x;
    for (int r = threadIdx.x; r < NR; r += blockDim.x) {
        sA[r] = g_A[s * NR + r];
        sR[r] = rbins[r];
    }
    __syncthreads();
    float dr = sR[1] - sR[0];
    float c = 4.f * PI_F * g_rho[s] * dr;
    for (int q = threadIdx.x; q < NQ; q += blockDim.x) {
        float qv = qbins[q];
        float acc = 0.f;
        for (int r = 0; r < NR; r++) {
            float qr = qv * sR[r];
            acc += sA[r] * (sinf(qr) / qr);
        }
        outS[s * NQ + q] = 1.f + c * acc;
    }
}

// ---------------------------------------------------------------------------
// Tetrahedral order parameter: warp per Si, last system only.
// Each lane scans O atoms keeping a sorted local top-4 (within cutoff),
// then 4 rounds of warp-argmin merge.
// ---------------------------------------------------------------------------
__global__ void __launch_bounds__(256)
k_qtet(const float* __restrict__ pos,
       const float* __restrict__ cell,
       int S, int N, float* __restrict__ outQ)
{
    int nsi = N / 3;
    int w = (int)((blockIdx.x * blockDim.x + threadIdx.x) >> 5);
    int lane = threadIdx.x & 31;
    if (w >= nsi) return;

    int s = S - 1;
    const float* pL = pos + (size_t)s * N * 3;
    const float* cc = cell + 9 * s;
    float c0 = cc[0], c1 = cc[1], c2 = cc[2];
    float c3 = cc[3], c4 = cc[4], c5 = cc[5];
    float c6 = cc[6], c7 = cc[7], c8 = cc[8];
    const float* iv = g_inv[s];
    float i0 = iv[0], i1 = iv[1], i2 = iv[2];
    float i3 = iv[3], i4 = iv[4], i5 = iv[5];
    float i6 = iv[6], i7 = iv[7], i8 = iv[8];

    float xs = pL[w * 3 + 0], ys = pL[w * 3 + 1], zs = pL[w * 3 + 2];

    float d4[4] = {INFINITY, INFINITY, INFINITY, INFINITY};
    float vx[4] = {0.f, 0.f, 0.f, 0.f};
    float vy[4] = {0.f, 0.f, 0.f, 0.f};
    float vz[4] = {0.f, 0.f, 0.f, 0.f};
    int cnt = 0;
    int nO = N - nsi;

    for (int o = lane; o < nO; o += 32) {
        const float* pO = pL + (size_t)(nsi + o) * 3;
        float dx = pO[0] - xs, dy = pO[1] - ys, dz = pO[2] - zs;
        float f0 = dx * i0 + dy * i3 + dz * i6;
        float f1 = dx * i1 + dy * i4 + dz * i7;
        float f2 = dx * i2 + dy * i5 + dz * i8;
        f0 -= rintf(f0); f1 -= rintf(f1); f2 -= rintf(f2);
        float gx = f0 * c0 + f1 * c3 + f2 * c6;
        float gy = f0 * c1 + f1 * c4 + f2 * c7;
        float gz = f0 * c2 + f1 * c5 + f2 * c8;
        float dd = sqrtf(gx * gx + gy * gy + gz * gz + 1e-12f);
        if (dd <= TET_CUTOFF) {
            cnt++;
            float nd = dd, nx = gx, ny = gy, nz = gz;
            #pragma unroll
            for (int p = 0; p < 4; p++) {
                if (nd < d4[p]) {
                    float tf;
                    tf = d4[p]; d4[p] = nd; nd = tf;
                    tf = vx[p]; vx[p] = nx; nx = tf;
                    tf = vy[p]; vy[p] = ny; ny = tf;
                    tf = vz[p]; vz[p] = nz; nz = tf;
                }
            }
        }
    }

    // total within count
    #pragma unroll
    for (int off = 16; off; off >>= 1)
        cnt += __shfl_xor_sync(0xFFFFFFFFu, cnt, off);

    // merge: 4 rounds of warp argmin on each lane's current head (d4[0])
    float ux[4], uy[4], uz[4];
    #pragma unroll
    for (int r = 0; r < 4; r++) {
        float v = d4[0];
        int src = lane;
        #pragma unroll
        for (int off = 16; off; off >>= 1) {
            float ov = __shfl_xor_sync(0xFFFFFFFFu, v, off);
            int os = __shfl_xor_sync(0xFFFFFFFFu, src, off);
            if (ov < v || (ov == v && os < src)) { v = ov; src = os; }
        }
        ux[r] = __shfl_sync(0xFFFFFFFFu, vx[0], src);
        uy[r] = __shfl_sync(0xFFFFFFFFu, vy[0], src);
        uz[r] = __shfl_sync(0xFFFFFFFFu, vz[0], src);
        if (lane == src) {
            d4[0] = d4[1]; d4[1] = d4[2]; d4[2] = d4[3]; d4[3] = INFINITY;
            vx[0] = vx[1]; vx[1] = vx[2]; vx[2] = vx[3];
            vy[0] = vy[1]; vy[1] = vy[2]; vy[2] = vy[3];
            vz[0] = vz[1]; vz[1] = vz[2]; vz[2] = vz[3];
        }
    }

    if (lane == 0) {
        #pragma unroll
        for (int k = 0; k < 4; k++) {
            float n = sqrtf(ux[k]*ux[k] + uy[k]*uy[k] + uz[k]*uz[k] + 1e-12f);
            ux[k] /= n; uy[k] /= n; uz[k] /= n;
        }
        const int jj[6] = {0, 0, 0, 1, 1, 2};
        const int kk[6] = {1, 2, 3, 2, 3, 3};
        float ssum = 0.f;
        #pragma unroll
        for (int p = 0; p < 6; p++) {
            int a = jj[p], b = kk[p];
            float cs = ux[a]*ux[b] + uy[a]*uy[b] + uz[a]*uz[b];
            cs = fminf(1.f, fmaxf(-1.f, cs));
            float tt = cs + (1.f / 3.f);
            ssum += tt * tt;
        }
        float q = 1.f - 0.375f * ssum;
        outQ[w] = (cnt >= 4) ? q : 0.f;
    }
}

// ---------------------------------------------------------------------------
extern "C" void kernel_launch(void* const* d_in, const int* in_sizes, int n_in,
                              void* d_out, int out_size)
{
    const float* pos   = (const float*)d_in[0];
    const float* cell  = (const float*)d_in[1];
    const float* rbins = (const float*)d_in[2];
    const float* qbins = (const float*)d_in[3];
    const int*   zn    = (const int*)d_in[4];

    int S  = in_sizes[1] / 9;
    int NR = in_sizes[2];
    int NQ = in_sizes[3];
    int N  = in_sizes[4];
    int nsi = N / 3;

    float* out  = (float*)d_out;
    float* outG = out;
    float* outT = out + (size_t)S * NR;
    float* outS = out + (size_t)2 * S * NR;
    float* outQ = out + (size_t)2 * S * NR + (size_t)S * NQ;

    k_setup<<<1, 256>>>(cell, zn, S, N, NR);

    int TI = (N + 255) / 256;
    k_pairs<<<S * TI * TI, 256>>>(pos, cell, rbins, N, NR, TI);

    k_final<<<S, 256>>>(rbins, N, NR, outG, outT);
    k_sq<<<S, 256>>>(rbins, qbins, NR, NQ, outS);

    int nwarps = nsi;
    int nblocks = (nwarps * 32 + 255) / 256;
    k_qtet<<<nblocks, 256>>>(pos, cell, S, N, outQ);
}

// round 3
// speedup vs baseline: 5.1800x; 5.1800x over previous
#include <cuda_runtime.h>
#include <math.h>
#include <stdint.h>

#define B_SI 4.1491f
#define B_O  5.803f
#define TET_CUTOFF 3.9f
#define PI_F 3.14159265358979323846f

#define MAXS 8
#define MAXNR 256
#define MAXNRF 2112     // NR*8 + 64 margin (NR<=256)
#define MAXN 4096
#define TS 128          // pair tile size

// device scratch (no allocations allowed)
__device__ float g_fine[MAXS * MAXNRF];
__device__ float g_A[MAXS * MAXNR];
__device__ float g_inv[MAXS][9];
__device__ float g_V[MAXS];
__device__ float g_rho[MAXS];
__device__ int   g_diag[MAXS];
__device__ float g_bn[MAXN];

// ---------------------------------------------------------------------------
// Setup: mean b, normalized b, cell inverses/dets, diagonal flag, zero fine hist
// ---------------------------------------------------------------------------
__global__ void k_setup(const float* __restrict__ cell,
                        const int* __restrict__ zn,
                        int S, int N)
{
    __shared__ float red[256];
    int t = threadIdx.x;

    float acc = 0.f;
    for (int i = t; i < N; i += 256) acc += (zn[i] == 14) ? B_SI : B_O;
    red[t] = acc;
    __syncthreads();
    for (int o = 128; o > 0; o >>= 1) {
        if (t < o) red[t] += red[t + o];
        __syncthreads();
    }
    float meanb = red[0] / (float)N;

    for (int i = t; i < N; i += 256)
        g_bn[i] = ((zn[i] == 14) ? B_SI : B_O) / meanb;

    for (int i = t; i < S * MAXNRF; i += 256) g_fine[i] = 0.f;

    if (t < S) {
        const float* a = cell + 9 * t;
        float det = a[0]*(a[4]*a[8]-a[5]*a[7])
                  - a[1]*(a[3]*a[8]-a[5]*a[6])
                  + a[2]*(a[3]*a[7]-a[4]*a[6]);
        float id = 1.f / det;
        float* inv = g_inv[t];
        inv[0] = (a[4]*a[8]-a[5]*a[7])*id;
        inv[1] = (a[2]*a[7]-a[1]*a[8])*id;
        inv[2] = (a[1]*a[5]-a[2]*a[4])*id;
        inv[3] = (a[5]*a[6]-a[3]*a[8])*id;
        inv[4] = (a[0]*a[8]-a[2]*a[6])*id;
        inv[5] = (a[2]*a[3]-a[0]*a[5])*id;
        inv[6] = (a[3]*a[7]-a[4]*a[6])*id;
        inv[7] = (a[1]*a[6]-a[0]*a[7])*id;
        inv[8] = (a[0]*a[4]-a[1]*a[3])*id;
        float V = fabsf(det);
        g_V[t]   = V;
        g_rho[t] = (float)N / V;
        float offd = fabsf(a[1]) + fabsf(a[2]) + fabsf(a[3])
                   + fabsf(a[5]) + fabsf(a[6]) + fabsf(a[7]);
        g_diag[t] = (offd == 0.f) ? 1 : 0;
    }
}

// ---------------------------------------------------------------------------
// Pair deposit: upper-triangle 128x128 tiles, weight 2x. CIC deposit onto a
// fine grid (h = dr/8). Per-block smem fine histogram, then global merge.
// ---------------------------------------------------------------------------
__global__ void __launch_bounds__(TS)
k_pairs(const float* __restrict__ pos,
        const float* __restrict__ cell,
        const float* __restrict__ rbins,
        int N, int NR, int TI)
{
    __shared__ float s_fine[MAXNRF];
    __shared__ float s_jx[TS], s_jy[TS], s_jz[TS], s_jb[TS];

    int t = threadIdx.x;
    int TP = TI * (TI + 1) / 2;
    int s  = blockIdx.x / TP;
    int tp = blockIdx.x % TP;
    // decode upper-triangle (it <= jt)
    int it = 0, rem = tp;
    while (rem >= TI - it) { rem -= TI - it; it++; }
    int jt = it + rem;

    int NRF = NR * 8 + 64;
    for (int k = t; k < NRF; k += TS) s_fine[k] = 0.f;

    float r0 = rbins[0];
    float rmax = rbins[NR - 1];
    float dr = (rmax - r0) / (float)(NR - 1);
    float h = dr * 0.125f;
    float inv_h = 1.f / h;
    float lim = rmax + 3.25f * dr;    // 6.5 sigma window
    float lim2 = lim * lim;

    int diag_cell = g_diag[s];
    const float* cc = cell + 9 * s;
    float c0 = cc[0], c4 = cc[4], c8 = cc[8];
    float c1 = cc[1], c2 = cc[2], c3 = cc[3], c5 = cc[5], c6 = cc[6], c7 = cc[7];
    const float* iv = g_inv[s];
    float i0 = iv[0], i1 = iv[1], i2 = iv[2];
    float i3 = iv[3], i4 = iv[4], i5 = iv[5];
    float i6 = iv[6], i7 = iv[7], i8 = iv[8];
    float Lx = c0, Ly = c4, Lz = c8;
    float iLx = 1.f / Lx, iLy = 1.f / Ly, iLz = 1.f / Lz;

    int jbase = jt * TS;
    int jn = N - jbase; if (jn > TS) jn = TS;
    if (t < jn) {
        const float* p = pos + ((size_t)s * N + jbase + t) * 3;
        s_jx[t] = p[0]; s_jy[t] = p[1]; s_jz[t] = p[2];
        s_jb[t] = g_bn[jbase + t];
    }
    __syncthreads();

    int i = it * TS + t;
    if (i < N) {
        const float* p = pos + ((size_t)s * N + i) * 3;
        float xi = p[0], yi = p[1], zi = p[2];
        float bi2 = 2.f * g_bn[i];

        int j0 = (it == jt) ? (t + 1) : 0;

        if (diag_cell) {
            for (int j = j0; j < jn; j++) {
                float dx = s_jx[j] - xi;
                float dy = s_jy[j] - yi;
                float dz = s_jz[j] - zi;
                dx -= Lx * rintf(dx * iLx);
                dy -= Ly * rintf(dy * iLy);
                dz -= Lz * rintf(dz * iLz);
                float d2 = dx*dx + dy*dy + dz*dz;
                if (d2 <= lim2) {
                    float dist = sqrtf(d2 + 1e-12f);
                    float u = (dist - r0) * inv_h + 32.f;
                    float mf = floorf(u);
                    int m = (int)mf;
                    float fr = u - mf;
                    float w2 = bi2 * s_jb[j];
                    atomicAdd(&s_fine[m],     w2 * (1.f - fr));
                    atomicAdd(&s_fine[m + 1], w2 * fr);
                }
            }
        } else {
            for (int j = j0; j < jn; j++) {
                float dx = s_jx[j] - xi;
                float dy = s_jy[j] - yi;
                float dz = s_jz[j] - zi;
                float f0 = dx*i0 + dy*i3 + dz*i6;
                float f1 = dx*i1 + dy*i4 + dz*i7;
                float f2 = dx*i2 + dy*i5 + dz*i8;
                f0 -= rintf(f0); f1 -= rintf(f1); f2 -= rintf(f2);
                float gx = f0*c0 + f1*c3 + f2*c6;
                float gy = f0*c1 + f1*c4 + f2*c7;
                float gz = f0*c2 + f1*c5 + f2*c8;
                float d2 = gx*gx + gy*gy + gz*gz;
                if (d2 <= lim2) {
                    float dist = sqrtf(d2 + 1e-12f);
                    float u = (dist - r0) * inv_h + 32.f;
                    float mf = floorf(u);
                    int m = (int)mf;
                    float fr = u - mf;
                    float w2 = bi2 * s_jb[j];
                    atomicAdd(&s_fine[m],     w2 * (1.f - fr));
                    atomicAdd(&s_fine[m + 1], w2 * fr);
                }
            }
        }
    }
    __syncthreads();

    float* gf = g_fine + (size_t)s * MAXNRF;
    for (int k = t; k < NRF; k += TS) {
        float v = s_fine[k];
        if (v != 0.f) atomicAdd(&gf[k], v);
    }
}

// ---------------------------------------------------------------------------
// Finalize: convolve fine hist with a deconvolution-matched Gaussian.
// CIC deposit == triangle(h) smoothing (variance h^2/6), so use
// sigma'^2 = sigma^2 - h^2/6 and amplitude scale sigma/sigma' — the composite
// triangle (x) N(sigma') matches the reference Gaussian through 2nd order
// (residual ~ h^4/(1440 sigma^4) ~ 3e-6).
// ---------------------------------------------------------------------------
__global__ void k_final(const float* __restrict__ rbins, int N, int NR,
                        float* __restrict__ outG, float* __restrict__ outT)
{
    __shared__ float sK[53];
    int s = blockIdx.x;
    int t = threadIdx.x;

    float r0 = rbins[0];
    float rmax = rbins[NR - 1];
    float dr = (rmax - r0) / (float)(NR - 1);
    float h = dr * 0.125f;
    float sigma = 0.5f * dr;
    float sigp = sqrtf(sigma * sigma - h * h / 6.f);

    if (t < 53) {
        float x = (float)(t - 26) * h / sigp;
        sK[t] = __expf(-0.5f * x * x);
    }
    __syncthreads();

    float kern = dr / (sigma * sqrtf(2.f * PI_F)) * (sigma / sigp);
    float V = g_V[s], rho = g_rho[s];
    float cG = V / ((float)N * (float)N * 4.f * PI_F * dr);
    const float* gf = g_fine + (size_t)s * MAXNRF;

    for (int r = t; r < NR; r += blockDim.x) {
        int base = r * 8 + 32;
        float acc = 0.f;
        #pragma unroll
        for (int tt = 0; tt < 53; tt++)
            acc += gf[base - 26 + tt] * sK[tt];
        float rv = rbins[r];
        float G = acc * kern * cG / (rv * rv);
        outG[s * NR + r] = G;
        outT[s * NR + r] = 4.f * PI_F * rho * rv * G;
        g_A[s * NR + r] = (G - 1.f) * rv * rv;
    }
}

// ---------------------------------------------------------------------------
// S_Q: one block per (s,q); r-parallel reduction.
// ---------------------------------------------------------------------------
__global__ void __launch_bounds__(64)
k_sq(const float* __restrict__ rbins,
     const float* __restrict__ qbins,
     int NR, int NQ, float* __restrict__ outS)
{
    __shared__ float red[2];
    int s = blockIdx.x / NQ;
    int q = blockIdx.x % NQ;
    int t = threadIdx.x;

    float r0 = rbins[0];
    float rmax = rbins[NR - 1];
    float dr = (rmax - r0) / (float)(NR - 1);
    float qv = qbins[q];

    float acc = 0.f;
    for (int r = t; r < NR; r += 64) {
        float qr = qv * rbins[r];
        acc += g_A[s * NR + r] * (__sinf(qr) / qr);
    }
    #pragma unroll
    for (int off = 16; off; off >>= 1)
        acc += __shfl_xor_sync(0xFFFFFFFFu, acc, off);
    if ((t & 31) == 0) red[t >> 5] = acc;
    __syncthreads();
    if (t == 0) {
        float c = 4.f * PI_F * g_rho[s] * dr;
        outS[s * NQ + q] = 1.f + c * (red[0] + red[1]);
    }
}

// ---------------------------------------------------------------------------
// Tetrahedral order parameter: warp per Si, last system only.
// ---------------------------------------------------------------------------
__global__ void __launch_bounds__(256)
k_qtet(const float* __restrict__ pos,
       const float* __restrict__ cell,
       int S, int N, float* __restrict__ outQ)
{
    int nsi = N / 3;
    int w = (int)((blockIdx.x * blockDim.x + threadIdx.x) >> 5);
    int lane = threadIdx.x & 31;
    if (w >= nsi) return;

    int s = S - 1;
    const float* pL = pos + (size_t)s * N * 3;
    const float* cc = cell + 9 * s;
    float c0 = cc[0], c1 = cc[1], c2 = cc[2];
    float c3 = cc[3], c4 = cc[4], c5 = cc[5];
    float c6 = cc[6], c7 = cc[7], c8 = cc[8];
    const float* iv = g_inv[s];
    float i0 = iv[0], i1 = iv[1], i2 = iv[2];
    float i3 = iv[3], i4 = iv[4], i5 = iv[5];
    float i6 = iv[6], i7 = iv[7], i8 = iv[8];

    float xs = pL[w * 3 + 0], ys = pL[w * 3 + 1], zs = pL[w * 3 + 2];

    float d4[4] = {INFINITY, INFINITY, INFINITY, INFINITY};
    float vx[4] = {0.f, 0.f, 0.f, 0.f};
    float vy[4] = {0.f, 0.f, 0.f, 0.f};
    float vz[4] = {0.f, 0.f, 0.f, 0.f};
    int cnt = 0;
    int nO = N - nsi;

    for (int o = lane; o < nO; o += 32) {
        const float* pO = pL + (size_t)(nsi + o) * 3;
        float dx = pO[0] - xs, dy = pO[1] - ys, dz = pO[2] - zs;
        float f0 = dx * i0 + dy * i3 + dz * i6;
        float f1 = dx * i1 + dy * i4 + dz * i7;
        float f2 = dx * i2 + dy * i5 + dz * i8;
        f0 -= rintf(f0); f1 -= rintf(f1); f2 -= rintf(f2);
        float gx = f0 * c0 + f1 * c3 + f2 * c6;
        float gy = f0 * c1 + f1 * c4 + f2 * c7;
        float gz = f0 * c2 + f1 * c5 + f2 * c8;
        float dd = sqrtf(gx * gx + gy * gy + gz * gz + 1e-12f);
        if (dd <= TET_CUTOFF) {
            cnt++;
            float nd = dd, nx = gx, ny = gy, nz = gz;
            #pragma unroll
            for (int p = 0; p < 4; p++) {
                if (nd < d4[p]) {
                    float tf;
                    tf = d4[p]; d4[p] = nd; nd = tf;
                    tf = vx[p]; vx[p] = nx; nx = tf;
                    tf = vy[p]; vy[p] = ny; ny = tf;
                    tf = vz[p]; vz[p] = nz; nz = tf;
                }
            }
        }
    }

    #pragma unroll
    for (int off = 16; off; off >>= 1)
        cnt += __shfl_xor_sync(0xFFFFFFFFu, cnt, off);

    float ux[4], uy[4], uz[4];
    #pragma unroll
    for (int r = 0; r < 4; r++) {
        float v = d4[0];
        int src = lane;
        #pragma unroll
        for (int off = 16; off; off >>= 1) {
            float ov = __shfl_xor_sync(0xFFFFFFFFu, v, off);
            int os = __shfl_xor_sync(0xFFFFFFFFu, src, off);
            if (ov < v || (ov == v && os < src)) { v = ov; src = os; }
        }
        ux[r] = __shfl_sync(0xFFFFFFFFu, vx[0], src);
        uy[r] = __shfl_sync(0xFFFFFFFFu, vy[0], src);
        uz[r] = __shfl_sync(0xFFFFFFFFu, vz[0], src);
        if (lane == src) {
            d4[0] = d4[1]; d4[1] = d4[2]; d4[2] = d4[3]; d4[3] = INFINITY;
            vx[0] = vx[1]; vx[1] = vx[2]; vx[2] = vx[3];
            vy[0] = vy[1]; vy[1] = vy[2]; vy[2] = vy[3];
            vz[0] = vz[1]; vz[1] = vz[2]; vz[2] = vz[3];
        }
    }

    if (lane == 0) {
        #pragma unroll
        for (int k = 0; k < 4; k++) {
            float n = sqrtf(ux[k]*ux[k] + uy[k]*uy[k] + uz[k]*uz[k] + 1e-12f);
            ux[k] /= n; uy[k] /= n; uz[k] /= n;
        }
        const int jj[6] = {0, 0, 0, 1, 1, 2};
        const int kk[6] = {1, 2, 3, 2, 3, 3};
        float ssum = 0.f;
        #pragma unroll
        for (int p = 0; p < 6; p++) {
            int a = jj[p], b = kk[p];
            float cs = ux[a]*ux[b] + uy[a]*uy[b] + uz[a]*uz[b];
            cs = fminf(1.f, fmaxf(-1.f, cs));
            float tt = cs + (1.f / 3.f);
            ssum += tt * tt;
        }
        float q = 1.f - 0.375f * ssum;
        outQ[w] = (cnt >= 4) ? q : 0.f;
    }
}

// ---------------------------------------------------------------------------
extern "C" void kernel_launch(void* const* d_in, const int* in_sizes, int n_in,
                              void* d_out, int out_size)
{
    const float* pos   = (const float*)d_in[0];
    const float* cell  = (const float*)d_in[1];
    const float* rbins = (const float*)d_in[2];
    const float* qbins = (const float*)d_in[3];
    const int*   zn    = (const int*)d_in[4];

    int S  = in_sizes[1] / 9;
    int NR = in_sizes[2];
    int NQ = in_sizes[3];
    int N  = in_sizes[4];
    int nsi = N / 3;

    float* out  = (float*)d_out;
    float* outG = out;
    float* outT = out + (size_t)S * NR;
    float* outS = out + (size_t)2 * S * NR;
    float* outQ = out + (size_t)2 * S * NR + (size_t)S * NQ;

    k_setup<<<1, 256>>>(cell, zn, S, N);

    int TI = (N + TS - 1) / TS;
    int TP = TI * (TI + 1) / 2;
    k_pairs<<<S * TP, TS>>>(pos, cell, rbins, N, NR, TI);

    k_final<<<S, 256>>>(rbins, N, NR, outG, outT);
    k_sq<<<S * NQ, 64>>>(rbins, qbins, NR, NQ, outS);

    int nblocks = (nsi * 32 + 255) / 256;
    k_qtet<<<nblocks, 256>>>(pos, cell, S, N, outQ);
}